// round 2
// baseline (speedup 1.0000x reference)
#include <cuda_runtime.h>
#include <math.h>

// Problem constants
#define BB   2
#define SS   2048
#define EE   2048
#define HH   32
#define DKQ  32
#define DVV  32
#define RK   1024
#define MM   (BB*SS)   // 4096

// Scratch (no cudaMalloc allowed)
__device__ float g_q[MM * RK];
__device__ float g_k[MM * RK];
__device__ float g_v[MM * RK];
__device__ float g_att[MM * RK];

// ---------------------------------------------------------------------------
// C[m][n] = alpha * ( sum_k A[m][k]*W[n][k] + bias[n] )
// A: (Md x Kd) row-major, W: (Nd x Kd) row-major (i.e. C = A @ W^T)
// Tile: BM=64, BN=64, BK=16; 256 threads; 4x4 micro-tile per thread.
// ---------------------------------------------------------------------------
__global__ __launch_bounds__(256) void gemm_nt_bias(
    const float* __restrict__ A, const float* __restrict__ W,
    const float* __restrict__ bias, float* __restrict__ C,
    int Md, int Nd, int Kd, float alpha)
{
    __shared__ float As[16][64];
    __shared__ float Bs[16][64];

    const int bm = blockIdx.y * 64;
    const int bn = blockIdx.x * 64;
    const int tid = threadIdx.x;

    const int tm = (tid >> 4) << 2;   // 0..60 step 4
    const int tn = (tid & 15) << 2;   // 0..60 step 4

    const int lr = tid >> 2;          // 0..63 (tile row for loads)
    const int lc = (tid & 3) << 2;    // 0,4,8,12 (k offset for loads)

    float acc[4][4];
    #pragma unroll
    for (int i = 0; i < 4; i++)
        #pragma unroll
        for (int j = 0; j < 4; j++) acc[i][j] = 0.f;

    const float* Ap = A + (size_t)(bm + lr) * Kd + lc;
    const float* Wp = W + (size_t)(bn + lr) * Kd + lc;

    for (int k0 = 0; k0 < Kd; k0 += 16) {
        float4 av = *(const float4*)(Ap + k0);
        float4 wv = *(const float4*)(Wp + k0);
        As[lc + 0][lr] = av.x; As[lc + 1][lr] = av.y;
        As[lc + 2][lr] = av.z; As[lc + 3][lr] = av.w;
        Bs[lc + 0][lr] = wv.x; Bs[lc + 1][lr] = wv.y;
        Bs[lc + 2][lr] = wv.z; Bs[lc + 3][lr] = wv.w;
        __syncthreads();

        #pragma unroll
        for (int k = 0; k < 16; k++) {
            float ar[4], br[4];
            *(float4*)ar = *(const float4*)&As[k][tm];
            *(float4*)br = *(const float4*)&Bs[k][tn];
            #pragma unroll
            for (int i = 0; i < 4; i++)
                #pragma unroll
                for (int j = 0; j < 4; j++)
                    acc[i][j] += ar[i] * br[j];
        }
        __syncthreads();
    }

    #pragma unroll
    for (int i = 0; i < 4; i++) {
        float* cp = C + (size_t)(bm + tm + i) * Nd + bn + tn;
        #pragma unroll
        for (int j = 0; j < 4; j++)
            cp[j] = alpha * (acc[i][j] + bias[bn + tn + j]);
    }
}

// ---------------------------------------------------------------------------
// Flash attention. One block = one (b, h, q-tile of 64 rows).
// 256 threads: row = tid/4 (0..63), 4 threads per row.
//   - S phase: each thread computes 16 score columns of its row.
//   - PV phase: each thread accumulates 8 of the 32 dv columns of its row.
// Online softmax state (m_i, l_i) replicated across the 4 threads of a row
// (kept consistent via shfl reductions within the 4-lane group).
// Causal tile skip: only k-tiles with k0 <= q0+63 are processed (mask is
// causal by construction); the additive mask from memory is still applied
// on every processed tile.
// ---------------------------------------------------------------------------
__global__ __launch_bounds__(256) void flash_attn(const float* __restrict__ mask)
{
    __shared__ float Qs[64][33];
    __shared__ float Ks[64][33];
    __shared__ float Vs[64][32];
    __shared__ float Ps[64][65];

    const int b  = blockIdx.z;
    const int h  = blockIdx.y;
    const int qi = blockIdx.x;
    const int q0 = qi * 64;

    const int tid = threadIdx.x;
    const int row = tid >> 2;
    const int cg  = tid & 3;
    const int cbase = cg * 16;
    const int dvb   = cg * 8;

    // Load Q tile
    for (int e = tid; e < 64 * 32; e += 256) {
        int r = e >> 5, d = e & 31;
        Qs[r][d] = g_q[((size_t)(b * SS + q0 + r)) * RK + h * DKQ + d];
    }

    float m_i = -INFINITY, l_i = 0.f;
    float o[8];
    #pragma unroll
    for (int j = 0; j < 8; j++) o[j] = 0.f;

    const int ntiles = qi + 1;  // causal
    for (int t = 0; t < ntiles; t++) {
        const int k0 = t * 64;
        __syncthreads();   // previous iteration's K/V consumers done
        for (int e = tid; e < 64 * 32; e += 256) {
            int r = e >> 5, d = e & 31;
            size_t gi = ((size_t)(b * SS + k0 + r)) * RK + h * DKQ + d;
            Ks[r][d] = g_k[gi];
            Vs[r][d] = g_v[gi];
        }
        __syncthreads();

        // ---- scores ----
        float s[16];
        #pragma unroll
        for (int j = 0; j < 16; j++) s[j] = 0.f;
        #pragma unroll
        for (int d = 0; d < 32; d++) {
            float qd = Qs[row][d];
            #pragma unroll
            for (int j = 0; j < 16; j++)
                s[j] += qd * Ks[cbase + j][d];
        }

        const float* mrow = mask + ((size_t)b * SS + (q0 + row)) * SS + k0 + cbase;
        float tmax = -INFINITY;
        #pragma unroll
        for (int j = 0; j < 16; j++) {
            s[j] = fmaxf(s[j] + mrow[j], -3.402823466e38f);
            tmax = fmaxf(tmax, s[j]);
        }
        tmax = fmaxf(tmax, __shfl_xor_sync(0xffffffffu, tmax, 1));
        tmax = fmaxf(tmax, __shfl_xor_sync(0xffffffffu, tmax, 2));

        const float m_new = fmaxf(m_i, tmax);
        const float scale = __expf(m_i - m_new);

        float lsum = 0.f;
        #pragma unroll
        for (int j = 0; j < 16; j++) {
            float p = __expf(s[j] - m_new);
            Ps[row][cbase + j] = p;
            lsum += p;
        }
        lsum += __shfl_xor_sync(0xffffffffu, lsum, 1);
        lsum += __shfl_xor_sync(0xffffffffu, lsum, 2);

        l_i = l_i * scale + lsum;
        m_i = m_new;

        #pragma unroll
        for (int j = 0; j < 8; j++) o[j] *= scale;

        __syncwarp();   // Ps written by the row's 4 lanes (same warp)
        for (int k = 0; k < 64; k++) {
            float p = Ps[row][k];
            #pragma unroll
            for (int j = 0; j < 8; j++)
                o[j] += p * Vs[k][dvb + j];
        }
        __syncwarp();   // Ps read complete before next iteration's writes
    }

    const float inv = 1.f / l_i;
    size_t ob = ((size_t)(b * SS + q0 + row)) * RK + h * DVV + dvb;
    #pragma unroll
    for (int j = 0; j < 8; j++)
        g_att[ob + j] = o[j] * inv;
}

// ---------------------------------------------------------------------------
extern "C" void kernel_launch(void* const* d_in, const int* in_sizes, int n_in,
                              void* d_out, int out_size)
{
    const float* hidden = (const float*)d_in[0];
    const float* mask   = (const float*)d_in[1];
    const float* Wq     = (const float*)d_in[2];
    const float* bq     = (const float*)d_in[3];
    const float* Wk     = (const float*)d_in[4];
    const float* bk     = (const float*)d_in[5];
    const float* Wv     = (const float*)d_in[6];
    const float* bv     = (const float*)d_in[7];
    const float* Wo     = (const float*)d_in[8];
    const float* bo     = (const float*)d_in[9];
    float* out = (float*)d_out;

    float* q = nullptr; float* k = nullptr; float* v = nullptr; float* att = nullptr;
    cudaGetSymbolAddress((void**)&q,   g_q);
    cudaGetSymbolAddress((void**)&k,   g_k);
    cudaGetSymbolAddress((void**)&v,   g_v);
    cudaGetSymbolAddress((void**)&att, g_att);

    const float scaling = 0.125f;  // 64^-0.5 (original head dim)

    // Projections: (4096 x 2048) @ (1024 x 2048)^T -> (4096 x 1024)
    {
        dim3 grid(RK / 64, MM / 64);
        gemm_nt_bias<<<grid, 256>>>(hidden, Wq, bq, q, MM, RK, EE, scaling);
        gemm_nt_bias<<<grid, 256>>>(hidden, Wk, bk, k, MM, RK, EE, 1.0f);
        gemm_nt_bias<<<grid, 256>>>(hidden, Wv, bv, v, MM, RK, EE, 1.0f);
    }

    // Attention
    {
        dim3 grid(SS / 64, HH, BB);
        flash_attn<<<grid, 256>>>(mask);
    }

    // Output projection: (4096 x 1024) @ (2048 x 1024)^T -> (4096 x 2048)
    {
        dim3 grid(EE / 64, MM / 64);
        gemm_nt_bias<<<grid, 256>>>(att, Wo, bo, out, MM, EE, RK, 1.0f);
    }
}

// round 4
// speedup vs baseline: 1.0002x; 1.0002x over previous
#include <cuda_runtime.h>
#include <math.h>

// Problem constants
#define BB   2
#define SS   2048
#define EE   2048
#define HH   32
#define DKQ  32
#define DVV  32
#define RK   1024
#define MM   (BB*SS)   // 4096

// Scratch (no cudaMalloc allowed)
__device__ float g_q[MM * RK];
__device__ float g_k[MM * RK];
__device__ float g_v[MM * RK];
__device__ float g_att[MM * RK];

// ---------------------------------------------------------------------------
// C[m][n] = alpha * ( sum_k A[m][k]*W[n][k] + bias[n] )
// A: (Md x Kd) row-major, W: (Nd x Kd) row-major (i.e. C = A @ W^T)
// Tile: BM=64, BN=64, BK=16; 256 threads; 4x4 micro-tile per thread.
// ---------------------------------------------------------------------------
__global__ __launch_bounds__(256) void gemm_nt_bias(
    const float* __restrict__ A, const float* __restrict__ W,
    const float* __restrict__ bias, float* __restrict__ C,
    int Md, int Nd, int Kd, float alpha)
{
    __shared__ float As[16][64];
    __shared__ float Bs[16][64];

    const int bm = blockIdx.y * 64;
    const int bn = blockIdx.x * 64;
    const int tid = threadIdx.x;

    const int tm = (tid >> 4) << 2;   // 0..60 step 4
    const int tn = (tid & 15) << 2;   // 0..60 step 4

    const int lr = tid >> 2;          // 0..63 (tile row for loads)
    const int lc = (tid & 3) << 2;    // 0,4,8,12 (k offset for loads)

    float acc[4][4];
    #pragma unroll
    for (int i = 0; i < 4; i++)
        #pragma unroll
        for (int j = 0; j < 4; j++) acc[i][j] = 0.f;

    const float* Ap = A + (size_t)(bm + lr) * Kd + lc;
    const float* Wp = W + (size_t)(bn + lr) * Kd + lc;

    for (int k0 = 0; k0 < Kd; k0 += 16) {
        float4 av = *(const float4*)(Ap + k0);
        float4 wv = *(const float4*)(Wp + k0);
        As[lc + 0][lr] = av.x; As[lc + 1][lr] = av.y;
        As[lc + 2][lr] = av.z; As[lc + 3][lr] = av.w;
        Bs[lc + 0][lr] = wv.x; Bs[lc + 1][lr] = wv.y;
        Bs[lc + 2][lr] = wv.z; Bs[lc + 3][lr] = wv.w;
        __syncthreads();

        #pragma unroll
        for (int k = 0; k < 16; k++) {
            float ar[4], br[4];
            *(float4*)ar = *(const float4*)&As[k][tm];
            *(float4*)br = *(const float4*)&Bs[k][tn];
            #pragma unroll
            for (int i = 0; i < 4; i++)
                #pragma unroll
                for (int j = 0; j < 4; j++)
                    acc[i][j] += ar[i] * br[j];
        }
        __syncthreads();
    }

    #pragma unroll
    for (int i = 0; i < 4; i++) {
        float* cp = C + (size_t)(bm + tm + i) * Nd + bn + tn;
        #pragma unroll
        for (int j = 0; j < 4; j++)
            cp[j] = alpha * (acc[i][j] + bias[bn + tn + j]);
    }
}

// ---------------------------------------------------------------------------
// Flash attention. One block = one (b, h, q-tile of 64 rows).
// 256 threads: row = tid/4 (0..63), 4 threads per row.
//   - S phase: each thread computes 16 score columns of its row.
//   - PV phase: each thread accumulates 8 of the 32 dv columns of its row.
// Online softmax state (m_i, l_i) replicated across the 4 threads of a row
// (kept consistent via shfl reductions within the 4-lane group).
// Causal tile skip: only k-tiles with k0 <= q0+63 are processed (mask is
// causal by construction); the additive mask from memory is still applied
// on every processed tile.
// ---------------------------------------------------------------------------
__global__ __launch_bounds__(256) void flash_attn(const float* __restrict__ mask)
{
    __shared__ float Qs[64][33];
    __shared__ float Ks[64][33];
    __shared__ float Vs[64][32];
    __shared__ float Ps[64][65];

    const int b  = blockIdx.z;
    const int h  = blockIdx.y;
    const int qi = blockIdx.x;
    const int q0 = qi * 64;

    const int tid = threadIdx.x;
    const int row = tid >> 2;
    const int cg  = tid & 3;
    const int cbase = cg * 16;
    const int dvb   = cg * 8;

    // Load Q tile
    for (int e = tid; e < 64 * 32; e += 256) {
        int r = e >> 5, d = e & 31;
        Qs[r][d] = g_q[((size_t)(b * SS + q0 + r)) * RK + h * DKQ + d];
    }

    float m_i = -INFINITY, l_i = 0.f;
    float o[8];
    #pragma unroll
    for (int j = 0; j < 8; j++) o[j] = 0.f;

    const int ntiles = qi + 1;  // causal
    for (int t = 0; t < ntiles; t++) {
        const int k0 = t * 64;
        __syncthreads();   // previous iteration's K/V consumers done
        for (int e = tid; e < 64 * 32; e += 256) {
            int r = e >> 5, d = e & 31;
            size_t gi = ((size_t)(b * SS + k0 + r)) * RK + h * DKQ + d;
            Ks[r][d] = g_k[gi];
            Vs[r][d] = g_v[gi];
        }
        __syncthreads();

        // ---- scores ----
        float s[16];
        #pragma unroll
        for (int j = 0; j < 16; j++) s[j] = 0.f;
        #pragma unroll
        for (int d = 0; d < 32; d++) {
            float qd = Qs[row][d];
            #pragma unroll
            for (int j = 0; j < 16; j++)
                s[j] += qd * Ks[cbase + j][d];
        }

        const float* mrow = mask + ((size_t)b * SS + (q0 + row)) * SS + k0 + cbase;
        float tmax = -INFINITY;
        #pragma unroll
        for (int j = 0; j < 16; j++) {
            s[j] = fmaxf(s[j] + mrow[j], -3.402823466e38f);
            tmax = fmaxf(tmax, s[j]);
        }
        tmax = fmaxf(tmax, __shfl_xor_sync(0xffffffffu, tmax, 1));
        tmax = fmaxf(tmax, __shfl_xor_sync(0xffffffffu, tmax, 2));

        const float m_new = fmaxf(m_i, tmax);
        const float scale = __expf(m_i - m_new);

        float lsum = 0.f;
        #pragma unroll
        for (int j = 0; j < 16; j++) {
            float p = __expf(s[j] - m_new);
            Ps[row][cbase + j] = p;
            lsum += p;
        }
        lsum += __shfl_xor_sync(0xffffffffu, lsum, 1);
        lsum += __shfl_xor_sync(0xffffffffu, lsum, 2);

        l_i = l_i * scale + lsum;
        m_i = m_new;

        #pragma unroll
        for (int j = 0; j < 8; j++) o[j] *= scale;

        __syncwarp();   // Ps written by the row's 4 lanes (same warp)
        for (int k = 0; k < 64; k++) {
            float p = Ps[row][k];
            #pragma unroll
            for (int j = 0; j < 8; j++)
                o[j] += p * Vs[k][dvb + j];
        }
        __syncwarp();   // Ps read complete before next iteration's writes
    }

    const float inv = 1.f / l_i;
    size_t ob = ((size_t)(b * SS + q0 + row)) * RK + h * DVV + dvb;
    #pragma unroll
    for (int j = 0; j < 8; j++)
        g_att[ob + j] = o[j] * inv;
}

// ---------------------------------------------------------------------------
extern "C" void kernel_launch(void* const* d_in, const int* in_sizes, int n_in,
                              void* d_out, int out_size)
{
    const float* hidden = (const float*)d_in[0];
    const float* mask   = (const float*)d_in[1];
    const float* Wq     = (const float*)d_in[2];
    const float* bq     = (const float*)d_in[3];
    const float* Wk     = (const float*)d_in[4];
    const float* bk     = (const float*)d_in[5];
    const float* Wv     = (const float*)d_in[6];
    const float* bv     = (const float*)d_in[7];
    const float* Wo     = (const float*)d_in[8];
    const float* bo     = (const float*)d_in[9];
    float* out = (float*)d_out;

    float* q = nullptr; float* k = nullptr; float* v = nullptr; float* att = nullptr;
    cudaGetSymbolAddress((void**)&q,   g_q);
    cudaGetSymbolAddress((void**)&k,   g_k);
    cudaGetSymbolAddress((void**)&v,   g_v);
    cudaGetSymbolAddress((void**)&att, g_att);

    const float scaling = 0.125f;  // 64^-0.5 (original head dim)

    // Projections: (4096 x 2048) @ (1024 x 2048)^T -> (4096 x 1024)
    {
        dim3 grid(RK / 64, MM / 64);
        gemm_nt_bias<<<grid, 256>>>(hidden, Wq, bq, q, MM, RK, EE, scaling);
        gemm_nt_bias<<<grid, 256>>>(hidden, Wk, bk, k, MM, RK, EE, 1.0f);
        gemm_nt_bias<<<grid, 256>>>(hidden, Wv, bv, v, MM, RK, EE, 1.0f);
    }

    // Attention
    {
        dim3 grid(SS / 64, HH, BB);
        flash_attn<<<grid, 256>>>(mask);
    }

    // Output projection: (4096 x 1024) @ (2048 x 1024)^T -> (4096 x 2048)
    {
        dim3 grid(EE / 64, MM / 64);
        gemm_nt_bias<<<grid, 256>>>(att, Wo, bo, out, MM, EE, RK, 1.0f);
    }
}

// round 5
// speedup vs baseline: 1.0084x; 1.0082x over previous
#include <cuda_runtime.h>
#include <math.h>

// Problem constants
#define BB   2
#define SS   2048
#define EE   2048
#define HH   32
#define DKQ  32
#define DVV  32
#define RK   1024
#define MM   (BB*SS)   // 4096

// Scratch (no cudaMalloc allowed)
__device__ float g_q[MM * RK];
__device__ float g_k[MM * RK];
__device__ float g_v[MM * RK];
__device__ float g_att[MM * RK];

// ---------------------------------------------------------------------------
// C[m][n] = alpha * ( sum_k A[m][k]*W[n][k] + bias[n] )
// A: (Md x Kd) row-major, W: (Nd x Kd) row-major (i.e. C = A @ W^T)
// Tile: BM=64, BN=64, BK=16; 256 threads; 4x4 micro-tile per thread.
// ---------------------------------------------------------------------------
__global__ __launch_bounds__(256) void gemm_nt_bias(
    const float* __restrict__ A, const float* __restrict__ W,
    const float* __restrict__ bias, float* __restrict__ C,
    int Md, int Nd, int Kd, float alpha)
{
    __shared__ float As[16][64];
    __shared__ float Bs[16][64];

    const int bm = blockIdx.y * 64;
    const int bn = blockIdx.x * 64;
    const int tid = threadIdx.x;

    const int tm = (tid >> 4) << 2;   // 0..60 step 4
    const int tn = (tid & 15) << 2;   // 0..60 step 4

    const int lr = tid >> 2;          // 0..63 (tile row for loads)
    const int lc = (tid & 3) << 2;    // 0,4,8,12 (k offset for loads)

    float acc[4][4];
    #pragma unroll
    for (int i = 0; i < 4; i++)
        #pragma unroll
        for (int j = 0; j < 4; j++) acc[i][j] = 0.f;

    const float* Ap = A + (size_t)(bm + lr) * Kd + lc;
    const float* Wp = W + (size_t)(bn + lr) * Kd + lc;

    for (int k0 = 0; k0 < Kd; k0 += 16) {
        float4 av = *(const float4*)(Ap + k0);
        float4 wv = *(const float4*)(Wp + k0);
        As[lc + 0][lr] = av.x; As[lc + 1][lr] = av.y;
        As[lc + 2][lr] = av.z; As[lc + 3][lr] = av.w;
        Bs[lc + 0][lr] = wv.x; Bs[lc + 1][lr] = wv.y;
        Bs[lc + 2][lr] = wv.z; Bs[lc + 3][lr] = wv.w;
        __syncthreads();

        #pragma unroll
        for (int k = 0; k < 16; k++) {
            float ar[4], br[4];
            *(float4*)ar = *(const float4*)&As[k][tm];
            *(float4*)br = *(const float4*)&Bs[k][tn];
            #pragma unroll
            for (int i = 0; i < 4; i++)
                #pragma unroll
                for (int j = 0; j < 4; j++)
                    acc[i][j] += ar[i] * br[j];
        }
        __syncthreads();
    }

    #pragma unroll
    for (int i = 0; i < 4; i++) {
        float* cp = C + (size_t)(bm + tm + i) * Nd + bn + tn;
        #pragma unroll
        for (int j = 0; j < 4; j++)
            cp[j] = alpha * (acc[i][j] + bias[bn + tn + j]);
    }
}

// ---------------------------------------------------------------------------
// Flash attention. One block = one (b, h, q-tile of 64 rows).
// 256 threads: row = tid/4 (0..63), 4 threads per row.
//   - S phase: each thread computes 16 score columns of its row.
//   - PV phase: each thread accumulates 8 of the 32 dv columns of its row.
// Online softmax state (m_i, l_i) replicated across the 4 threads of a row
// (kept consistent via shfl reductions within the 4-lane group).
// Causal tile skip: only k-tiles with k0 <= q0+63 are processed (mask is
// causal by construction); the additive mask from memory is still applied
// on every processed tile.
// ---------------------------------------------------------------------------
__global__ __launch_bounds__(256) void flash_attn(const float* __restrict__ mask)
{
    __shared__ float Qs[64][33];
    __shared__ float Ks[64][33];
    __shared__ float Vs[64][32];
    __shared__ float Ps[64][65];

    const int b  = blockIdx.z;
    const int h  = blockIdx.y;
    const int qi = blockIdx.x;
    const int q0 = qi * 64;

    const int tid = threadIdx.x;
    const int row = tid >> 2;
    const int cg  = tid & 3;
    const int cbase = cg * 16;
    const int dvb   = cg * 8;

    // Load Q tile
    for (int e = tid; e < 64 * 32; e += 256) {
        int r = e >> 5, d = e & 31;
        Qs[r][d] = g_q[((size_t)(b * SS + q0 + r)) * RK + h * DKQ + d];
    }

    float m_i = -INFINITY, l_i = 0.f;
    float o[8];
    #pragma unroll
    for (int j = 0; j < 8; j++) o[j] = 0.f;

    const int ntiles = qi + 1;  // causal
    for (int t = 0; t < ntiles; t++) {
        const int k0 = t * 64;
        __syncthreads();   // previous iteration's K/V consumers done
        for (int e = tid; e < 64 * 32; e += 256) {
            int r = e >> 5, d = e & 31;
            size_t gi = ((size_t)(b * SS + k0 + r)) * RK + h * DKQ + d;
            Ks[r][d] = g_k[gi];
            Vs[r][d] = g_v[gi];
        }
        __syncthreads();

        // ---- scores ----
        float s[16];
        #pragma unroll
        for (int j = 0; j < 16; j++) s[j] = 0.f;
        #pragma unroll
        for (int d = 0; d < 32; d++) {
            float qd = Qs[row][d];
            #pragma unroll
            for (int j = 0; j < 16; j++)
                s[j] += qd * Ks[cbase + j][d];
        }

        const float* mrow = mask + ((size_t)b * SS + (q0 + row)) * SS + k0 + cbase;
        float tmax = -INFINITY;
        #pragma unroll
        for (int j = 0; j < 16; j++) {
            s[j] = fmaxf(s[j] + mrow[j], -3.402823466e38f);
            tmax = fmaxf(tmax, s[j]);
        }
        tmax = fmaxf(tmax, __shfl_xor_sync(0xffffffffu, tmax, 1));
        tmax = fmaxf(tmax, __shfl_xor_sync(0xffffffffu, tmax, 2));

        const float m_new = fmaxf(m_i, tmax);
        const float scale = __expf(m_i - m_new);

        float lsum = 0.f;
        #pragma unroll
        for (int j = 0; j < 16; j++) {
            float p = __expf(s[j] - m_new);
            Ps[row][cbase + j] = p;
            lsum += p;
        }
        lsum += __shfl_xor_sync(0xffffffffu, lsum, 1);
        lsum += __shfl_xor_sync(0xffffffffu, lsum, 2);

        l_i = l_i * scale + lsum;
        m_i = m_new;

        #pragma unroll
        for (int j = 0; j < 8; j++) o[j] *= scale;

        __syncwarp();   // Ps written by the row's 4 lanes (same warp)
        for (int k = 0; k < 64; k++) {
            float p = Ps[row][k];
            #pragma unroll
            for (int j = 0; j < 8; j++)
                o[j] += p * Vs[k][dvb + j];
        }
        __syncwarp();   // Ps read complete before next iteration's writes
    }

    const float inv = 1.f / l_i;
    size_t ob = ((size_t)(b * SS + q0 + row)) * RK + h * DVV + dvb;
    #pragma unroll
    for (int j = 0; j < 8; j++)
        g_att[ob + j] = o[j] * inv;
}

// ---------------------------------------------------------------------------
extern "C" void kernel_launch(void* const* d_in, const int* in_sizes, int n_in,
                              void* d_out, int out_size)
{
    const float* hidden = (const float*)d_in[0];
    const float* mask   = (const float*)d_in[1];
    const float* Wq     = (const float*)d_in[2];
    const float* bq     = (const float*)d_in[3];
    const float* Wk     = (const float*)d_in[4];
    const float* bk     = (const float*)d_in[5];
    const float* Wv     = (const float*)d_in[6];
    const float* bv     = (const float*)d_in[7];
    const float* Wo     = (const float*)d_in[8];
    const float* bo     = (const float*)d_in[9];
    float* out = (float*)d_out;

    float* q = nullptr; float* k = nullptr; float* v = nullptr; float* att = nullptr;
    cudaGetSymbolAddress((void**)&q,   g_q);
    cudaGetSymbolAddress((void**)&k,   g_k);
    cudaGetSymbolAddress((void**)&v,   g_v);
    cudaGetSymbolAddress((void**)&att, g_att);

    const float scaling = 0.125f;  // 64^-0.5 (original head dim)

    // Projections: (4096 x 2048) @ (1024 x 2048)^T -> (4096 x 1024)
    {
        dim3 grid(RK / 64, MM / 64);
        gemm_nt_bias<<<grid, 256>>>(hidden, Wq, bq, q, MM, RK, EE, scaling);
        gemm_nt_bias<<<grid, 256>>>(hidden, Wk, bk, k, MM, RK, EE, 1.0f);
        gemm_nt_bias<<<grid, 256>>>(hidden, Wv, bv, v, MM, RK, EE, 1.0f);
    }

    // Attention
    {
        dim3 grid(SS / 64, HH, BB);
        flash_attn<<<grid, 256>>>(mask);
    }

    // Output projection: (4096 x 1024) @ (2048 x 1024)^T -> (4096 x 2048)
    {
        dim3 grid(EE / 64, MM / 64);
        gemm_nt_bias<<<grid, 256>>>(att, Wo, bo, out, MM, EE, RK, 1.0f);
    }
}

// round 6
// speedup vs baseline: 1.5381x; 1.5253x over previous
#include <cuda_runtime.h>
#include <math.h>
#include <stdint.h>

// Problem constants
#define BB   2
#define SS   2048
#define EE   2048
#define HH   32
#define DKQ  32
#define DVV  32
#define RK   1024
#define MM   (BB*SS)   // 4096

// Scratch (no cudaMalloc allowed)
__device__ float g_q[MM * RK];
__device__ float g_k[MM * RK];
__device__ float g_v[MM * RK];
__device__ float g_att[MM * RK];

// ---------------------------------------------------------------------------
// tf32 helpers
// ---------------------------------------------------------------------------
__device__ __forceinline__ uint32_t f2tf32(float x) {
    uint32_t r;
    asm("cvt.rna.tf32.f32 %0, %1;" : "=r"(r) : "f"(x));
    return r;
}

__device__ __forceinline__ void mma_tf32(float* c, const uint32_t* a, const uint32_t* b) {
    asm volatile(
        "mma.sync.aligned.m16n8k8.row.col.f32.tf32.tf32.f32 "
        "{%0,%1,%2,%3}, {%4,%5,%6,%7}, {%8,%9}, {%0,%1,%2,%3};"
        : "+f"(c[0]), "+f"(c[1]), "+f"(c[2]), "+f"(c[3])
        : "r"(a[0]), "r"(a[1]), "r"(a[2]), "r"(a[3]),
          "r"(b[0]), "r"(b[1]));
}

// ---------------------------------------------------------------------------
// tf32 tensor-core GEMM body:
//   C[m][n] = alpha * ( sum_k A[m][k]*W[n][k] + bias[n] )   (C = A @ W^T)
// Block tile 128x128, K-step 16. 256 threads = 8 warps in 2(M) x 4(N) grid,
// warp tile 64x32 = 4x4 grid of m16n8k8 MMAs.
// SMEM stride 20 floats: fragment loads hit all 32 banks (g*20+lq mod 32).
// Requires: Md % 128 == 0, Nd % 128 == 0, Kd % 16 == 0 (true for all calls).
// ---------------------------------------------------------------------------
__device__ __forceinline__ void gemm_body(
    const float* __restrict__ A, const float* __restrict__ W,
    const float* __restrict__ bias, float* __restrict__ C,
    int Nd, int Kd, float alpha, int bm, int bn)
{
    __shared__ uint32_t As[128][20];
    __shared__ uint32_t Bs[128][20];

    const int tid  = threadIdx.x;
    const int lane = tid & 31;
    const int warp = tid >> 5;
    const int g    = lane >> 2;      // 0..7
    const int lq   = lane & 3;       // 0..3
    const int wm   = (warp & 1) << 6;   // 0 or 64
    const int wn   = (warp >> 1) << 5;  // 0,32,64,96

    const int lrow = tid >> 2;          // 0..63
    const int lkg  = (tid & 3) << 2;    // 0,4,8,12

    const float* Ag0 = A + (size_t)(bm + lrow)      * Kd + lkg;
    const float* Ag1 = A + (size_t)(bm + lrow + 64) * Kd + lkg;
    const float* Wg0 = W + (size_t)(bn + lrow)      * Kd + lkg;
    const float* Wg1 = W + (size_t)(bn + lrow + 64) * Kd + lkg;

    float acc[4][4][4];
    #pragma unroll
    for (int i = 0; i < 4; i++)
        #pragma unroll
        for (int j = 0; j < 4; j++)
            #pragma unroll
            for (int e = 0; e < 4; e++) acc[i][j][e] = 0.f;

    // Prefetch first K-slab into registers
    float4 fa0 = *(const float4*)Ag0;
    float4 fa1 = *(const float4*)Ag1;
    float4 fb0 = *(const float4*)Wg0;
    float4 fb1 = *(const float4*)Wg1;

    for (int k0 = 0; k0 < Kd; k0 += 16) {
        // reg -> smem (convert to tf32 once per element here)
        As[lrow][lkg + 0] = f2tf32(fa0.x); As[lrow][lkg + 1] = f2tf32(fa0.y);
        As[lrow][lkg + 2] = f2tf32(fa0.z); As[lrow][lkg + 3] = f2tf32(fa0.w);
        As[lrow + 64][lkg + 0] = f2tf32(fa1.x); As[lrow + 64][lkg + 1] = f2tf32(fa1.y);
        As[lrow + 64][lkg + 2] = f2tf32(fa1.z); As[lrow + 64][lkg + 3] = f2tf32(fa1.w);
        Bs[lrow][lkg + 0] = f2tf32(fb0.x); Bs[lrow][lkg + 1] = f2tf32(fb0.y);
        Bs[lrow][lkg + 2] = f2tf32(fb0.z); Bs[lrow][lkg + 3] = f2tf32(fb0.w);
        Bs[lrow + 64][lkg + 0] = f2tf32(fb1.x); Bs[lrow + 64][lkg + 1] = f2tf32(fb1.y);
        Bs[lrow + 64][lkg + 2] = f2tf32(fb1.z); Bs[lrow + 64][lkg + 3] = f2tf32(fb1.w);
        __syncthreads();

        // prefetch next slab while MMAs run
        if (k0 + 16 < Kd) {
            Ag0 += 16; Ag1 += 16; Wg0 += 16; Wg1 += 16;
            fa0 = *(const float4*)Ag0;
            fa1 = *(const float4*)Ag1;
            fb0 = *(const float4*)Wg0;
            fb1 = *(const float4*)Wg1;
        }

        #pragma unroll
        for (int ks = 0; ks < 16; ks += 8) {
            uint32_t af[4][4], bf[4][2];
            #pragma unroll
            for (int i = 0; i < 4; i++) {
                const int r = wm + i * 16 + g;
                af[i][0] = As[r][ks + lq];
                af[i][1] = As[r + 8][ks + lq];
                af[i][2] = As[r][ks + lq + 4];
                af[i][3] = As[r + 8][ks + lq + 4];
            }
            #pragma unroll
            for (int j = 0; j < 4; j++) {
                const int n = wn + j * 8 + g;
                bf[j][0] = Bs[n][ks + lq];
                bf[j][1] = Bs[n][ks + lq + 4];
            }
            #pragma unroll
            for (int i = 0; i < 4; i++)
                #pragma unroll
                for (int j = 0; j < 4; j++)
                    mma_tf32(acc[i][j], af[i], bf[j]);
        }
        __syncthreads();
    }

    // Epilogue: C fragment layout m16n8: (g, 2*lq), (g, 2*lq+1), (g+8, ...)
    #pragma unroll
    for (int i = 0; i < 4; i++) {
        const int row = bm + wm + i * 16 + g;
        #pragma unroll
        for (int j = 0; j < 4; j++) {
            const int col = bn + wn + j * 8 + (lq << 1);
            const float b0 = bias[col], b1 = bias[col + 1];
            float* c0 = C + (size_t)row * Nd + col;
            float* c1 = C + (size_t)(row + 8) * Nd + col;
            c0[0] = alpha * (acc[i][j][0] + b0);
            c0[1] = alpha * (acc[i][j][1] + b1);
            c1[0] = alpha * (acc[i][j][2] + b0);
            c1[1] = alpha * (acc[i][j][3] + b1);
        }
    }
}

// Fused q/k/v projection: blockIdx.z selects the weight/bias/output triple.
__global__ __launch_bounds__(256) void gemm_qkv(
    const float* __restrict__ hidden,
    const float* __restrict__ Wq, const float* __restrict__ bq,
    const float* __restrict__ Wk, const float* __restrict__ bk,
    const float* __restrict__ Wv, const float* __restrict__ bv,
    float* __restrict__ q, float* __restrict__ k, float* __restrict__ v,
    float scaling)
{
    const float* W; const float* bias; float* C; float alpha;
    if (blockIdx.z == 0)      { W = Wq; bias = bq; C = q; alpha = scaling; }
    else if (blockIdx.z == 1) { W = Wk; bias = bk; C = k; alpha = 1.f; }
    else                      { W = Wv; bias = bv; C = v; alpha = 1.f; }
    gemm_body(hidden, W, bias, C, RK, EE, alpha, blockIdx.y * 128, blockIdx.x * 128);
}

__global__ __launch_bounds__(256) void gemm_o(
    const float* __restrict__ att,
    const float* __restrict__ Wo, const float* __restrict__ bo,
    float* __restrict__ out)
{
    gemm_body(att, Wo, bo, out, EE, RK, 1.f, blockIdx.y * 128, blockIdx.x * 128);
}

// ---------------------------------------------------------------------------
// Flash attention (unchanged from R5). One block = one (b, h, q-tile of 64).
// ---------------------------------------------------------------------------
__global__ __launch_bounds__(256) void flash_attn(const float* __restrict__ mask)
{
    __shared__ float Qs[64][33];
    __shared__ float Ks[64][33];
    __shared__ float Vs[64][32];
    __shared__ float Ps[64][65];

    const int b  = blockIdx.z;
    const int h  = blockIdx.y;
    const int qi = blockIdx.x;
    const int q0 = qi * 64;

    const int tid = threadIdx.x;
    const int row = tid >> 2;
    const int cg  = tid & 3;
    const int cbase = cg * 16;
    const int dvb   = cg * 8;

    for (int e = tid; e < 64 * 32; e += 256) {
        int r = e >> 5, d = e & 31;
        Qs[r][d] = g_q[((size_t)(b * SS + q0 + r)) * RK + h * DKQ + d];
    }

    float m_i = -INFINITY, l_i = 0.f;
    float o[8];
    #pragma unroll
    for (int j = 0; j < 8; j++) o[j] = 0.f;

    const int ntiles = qi + 1;  // causal
    for (int t = 0; t < ntiles; t++) {
        const int k0 = t * 64;
        __syncthreads();
        for (int e = tid; e < 64 * 32; e += 256) {
            int r = e >> 5, d = e & 31;
            size_t gi = ((size_t)(b * SS + k0 + r)) * RK + h * DKQ + d;
            Ks[r][d] = g_k[gi];
            Vs[r][d] = g_v[gi];
        }
        __syncthreads();

        float s[16];
        #pragma unroll
        for (int j = 0; j < 16; j++) s[j] = 0.f;
        #pragma unroll
        for (int d = 0; d < 32; d++) {
            float qd = Qs[row][d];
            #pragma unroll
            for (int j = 0; j < 16; j++)
                s[j] += qd * Ks[cbase + j][d];
        }

        const float* mrow = mask + ((size_t)b * SS + (q0 + row)) * SS + k0 + cbase;
        float tmax = -INFINITY;
        #pragma unroll
        for (int j = 0; j < 16; j++) {
            s[j] = fmaxf(s[j] + mrow[j], -3.402823466e38f);
            tmax = fmaxf(tmax, s[j]);
        }
        tmax = fmaxf(tmax, __shfl_xor_sync(0xffffffffu, tmax, 1));
        tmax = fmaxf(tmax, __shfl_xor_sync(0xffffffffu, tmax, 2));

        const float m_new = fmaxf(m_i, tmax);
        const float scale = __expf(m_i - m_new);

        float lsum = 0.f;
        #pragma unroll
        for (int j = 0; j < 16; j++) {
            float p = __expf(s[j] - m_new);
            Ps[row][cbase + j] = p;
            lsum += p;
        }
        lsum += __shfl_xor_sync(0xffffffffu, lsum, 1);
        lsum += __shfl_xor_sync(0xffffffffu, lsum, 2);

        l_i = l_i * scale + lsum;
        m_i = m_new;

        #pragma unroll
        for (int j = 0; j < 8; j++) o[j] *= scale;

        __syncwarp();
        for (int k = 0; k < 64; k++) {
            float p = Ps[row][k];
            #pragma unroll
            for (int j = 0; j < 8; j++)
                o[j] += p * Vs[k][dvb + j];
        }
        __syncwarp();
    }

    const float inv = 1.f / l_i;
    size_t ob = ((size_t)(b * SS + q0 + row)) * RK + h * DVV + dvb;
    #pragma unroll
    for (int j = 0; j < 8; j++)
        g_att[ob + j] = o[j] * inv;
}

// ---------------------------------------------------------------------------
extern "C" void kernel_launch(void* const* d_in, const int* in_sizes, int n_in,
                              void* d_out, int out_size)
{
    const float* hidden = (const float*)d_in[0];
    const float* mask   = (const float*)d_in[1];
    const float* Wq     = (const float*)d_in[2];
    const float* bq     = (const float*)d_in[3];
    const float* Wk     = (const float*)d_in[4];
    const float* bk     = (const float*)d_in[5];
    const float* Wv     = (const float*)d_in[6];
    const float* bv     = (const float*)d_in[7];
    const float* Wo     = (const float*)d_in[8];
    const float* bo     = (const float*)d_in[9];
    float* out = (float*)d_out;

    float* q = nullptr; float* k = nullptr; float* v = nullptr; float* att = nullptr;
    cudaGetSymbolAddress((void**)&q,   g_q);
    cudaGetSymbolAddress((void**)&k,   g_k);
    cudaGetSymbolAddress((void**)&v,   g_v);
    cudaGetSymbolAddress((void**)&att, g_att);

    const float scaling = 0.125f;  // 64^-0.5 (original head dim)

    // Fused projections: (4096 x 2048) @ (1024 x 2048)^T -> 3x (4096 x 1024)
    {
        dim3 grid(RK / 128, MM / 128, 3);
        gemm_qkv<<<grid, 256>>>(hidden, Wq, bq, Wk, bk, Wv, bv, q, k, v, scaling);
    }

    // Attention
    {
        dim3 grid(SS / 64, HH, BB);
        flash_attn<<<grid, 256>>>(mask);
    }

    // Output projection: (4096 x 1024) @ (2048 x 1024)^T -> (4096 x 2048)
    {
        dim3 grid(EE / 128, MM / 128);
        gemm_o<<<grid, 256>>>(att, Wo, bo, out);
    }
}

// round 7
// speedup vs baseline: 1.5408x; 1.0017x over previous
#include <cuda_runtime.h>
#include <math.h>
#include <stdint.h>

// Problem constants
#define BB   2
#define SS   2048
#define EE   2048
#define HH   32
#define DKQ  32
#define DVV  32
#define RK   1024
#define MM   (BB*SS)   // 4096

// Scratch (no cudaMalloc allowed)
__device__ float g_q[MM * RK];
__device__ float g_k[MM * RK];
__device__ float g_v[MM * RK];
__device__ float g_att[MM * RK];

// ---------------------------------------------------------------------------
// tf32 helpers
// ---------------------------------------------------------------------------
__device__ __forceinline__ uint32_t f2tf32(float x) {
    uint32_t r;
    asm("cvt.rna.tf32.f32 %0, %1;" : "=r"(r) : "f"(x));
    return r;
}

__device__ __forceinline__ void mma_tf32(float* c, const uint32_t* a, const uint32_t* b) {
    asm volatile(
        "mma.sync.aligned.m16n8k8.row.col.f32.tf32.tf32.f32 "
        "{%0,%1,%2,%3}, {%4,%5,%6,%7}, {%8,%9}, {%0,%1,%2,%3};"
        : "+f"(c[0]), "+f"(c[1]), "+f"(c[2]), "+f"(c[3])
        : "r"(a[0]), "r"(a[1]), "r"(a[2]), "r"(a[3]),
          "r"(b[0]), "r"(b[1]));
}

// ---------------------------------------------------------------------------
// tf32 tensor-core GEMM body:
//   C[m][n] = alpha * ( sum_k A[m][k]*W[n][k] + bias[n] )   (C = A @ W^T)
// Block tile 128x128, K-step 16. 256 threads = 8 warps in 2(M) x 4(N) grid,
// warp tile 64x32 = 4x4 grid of m16n8k8 MMAs.
// SMEM stride 20 floats: fragment loads hit all 32 banks (g*20+lq mod 32).
// Requires: Md % 128 == 0, Nd % 128 == 0, Kd % 16 == 0 (true for all calls).
// ---------------------------------------------------------------------------
__device__ __forceinline__ void gemm_body(
    const float* __restrict__ A, const float* __restrict__ W,
    const float* __restrict__ bias, float* __restrict__ C,
    int Nd, int Kd, float alpha, int bm, int bn)
{
    __shared__ uint32_t As[128][20];
    __shared__ uint32_t Bs[128][20];

    const int tid  = threadIdx.x;
    const int lane = tid & 31;
    const int warp = tid >> 5;
    const int g    = lane >> 2;      // 0..7
    const int lq   = lane & 3;       // 0..3
    const int wm   = (warp & 1) << 6;   // 0 or 64
    const int wn   = (warp >> 1) << 5;  // 0,32,64,96

    const int lrow = tid >> 2;          // 0..63
    const int lkg  = (tid & 3) << 2;    // 0,4,8,12

    const float* Ag0 = A + (size_t)(bm + lrow)      * Kd + lkg;
    const float* Ag1 = A + (size_t)(bm + lrow + 64) * Kd + lkg;
    const float* Wg0 = W + (size_t)(bn + lrow)      * Kd + lkg;
    const float* Wg1 = W + (size_t)(bn + lrow + 64) * Kd + lkg;

    float acc[4][4][4];
    #pragma unroll
    for (int i = 0; i < 4; i++)
        #pragma unroll
        for (int j = 0; j < 4; j++)
            #pragma unroll
            for (int e = 0; e < 4; e++) acc[i][j][e] = 0.f;

    // Prefetch first K-slab into registers
    float4 fa0 = *(const float4*)Ag0;
    float4 fa1 = *(const float4*)Ag1;
    float4 fb0 = *(const float4*)Wg0;
    float4 fb1 = *(const float4*)Wg1;

    for (int k0 = 0; k0 < Kd; k0 += 16) {
        // reg -> smem (convert to tf32 once per element here)
        As[lrow][lkg + 0] = f2tf32(fa0.x); As[lrow][lkg + 1] = f2tf32(fa0.y);
        As[lrow][lkg + 2] = f2tf32(fa0.z); As[lrow][lkg + 3] = f2tf32(fa0.w);
        As[lrow + 64][lkg + 0] = f2tf32(fa1.x); As[lrow + 64][lkg + 1] = f2tf32(fa1.y);
        As[lrow + 64][lkg + 2] = f2tf32(fa1.z); As[lrow + 64][lkg + 3] = f2tf32(fa1.w);
        Bs[lrow][lkg + 0] = f2tf32(fb0.x); Bs[lrow][lkg + 1] = f2tf32(fb0.y);
        Bs[lrow][lkg + 2] = f2tf32(fb0.z); Bs[lrow][lkg + 3] = f2tf32(fb0.w);
        Bs[lrow + 64][lkg + 0] = f2tf32(fb1.x); Bs[lrow + 64][lkg + 1] = f2tf32(fb1.y);
        Bs[lrow + 64][lkg + 2] = f2tf32(fb1.z); Bs[lrow + 64][lkg + 3] = f2tf32(fb1.w);
        __syncthreads();

        // prefetch next slab while MMAs run
        if (k0 + 16 < Kd) {
            Ag0 += 16; Ag1 += 16; Wg0 += 16; Wg1 += 16;
            fa0 = *(const float4*)Ag0;
            fa1 = *(const float4*)Ag1;
            fb0 = *(const float4*)Wg0;
            fb1 = *(const float4*)Wg1;
        }

        #pragma unroll
        for (int ks = 0; ks < 16; ks += 8) {
            uint32_t af[4][4], bf[4][2];
            #pragma unroll
            for (int i = 0; i < 4; i++) {
                const int r = wm + i * 16 + g;
                af[i][0] = As[r][ks + lq];
                af[i][1] = As[r + 8][ks + lq];
                af[i][2] = As[r][ks + lq + 4];
                af[i][3] = As[r + 8][ks + lq + 4];
            }
            #pragma unroll
            for (int j = 0; j < 4; j++) {
                const int n = wn + j * 8 + g;
                bf[j][0] = Bs[n][ks + lq];
                bf[j][1] = Bs[n][ks + lq + 4];
            }
            #pragma unroll
            for (int i = 0; i < 4; i++)
                #pragma unroll
                for (int j = 0; j < 4; j++)
                    mma_tf32(acc[i][j], af[i], bf[j]);
        }
        __syncthreads();
    }

    // Epilogue: C fragment layout m16n8: (g, 2*lq), (g, 2*lq+1), (g+8, ...)
    #pragma unroll
    for (int i = 0; i < 4; i++) {
        const int row = bm + wm + i * 16 + g;
        #pragma unroll
        for (int j = 0; j < 4; j++) {
            const int col = bn + wn + j * 8 + (lq << 1);
            const float b0 = bias[col], b1 = bias[col + 1];
            float* c0 = C + (size_t)row * Nd + col;
            float* c1 = C + (size_t)(row + 8) * Nd + col;
            c0[0] = alpha * (acc[i][j][0] + b0);
            c0[1] = alpha * (acc[i][j][1] + b1);
            c1[0] = alpha * (acc[i][j][2] + b0);
            c1[1] = alpha * (acc[i][j][3] + b1);
        }
    }
}

// Fused q/k/v projection: blockIdx.z selects the weight/bias/output triple.
__global__ __launch_bounds__(256) void gemm_qkv(
    const float* __restrict__ hidden,
    const float* __restrict__ Wq, const float* __restrict__ bq,
    const float* __restrict__ Wk, const float* __restrict__ bk,
    const float* __restrict__ Wv, const float* __restrict__ bv,
    float* __restrict__ q, float* __restrict__ k, float* __restrict__ v,
    float scaling)
{
    const float* W; const float* bias; float* C; float alpha;
    if (blockIdx.z == 0)      { W = Wq; bias = bq; C = q; alpha = scaling; }
    else if (blockIdx.z == 1) { W = Wk; bias = bk; C = k; alpha = 1.f; }
    else                      { W = Wv; bias = bv; C = v; alpha = 1.f; }
    gemm_body(hidden, W, bias, C, RK, EE, alpha, blockIdx.y * 128, blockIdx.x * 128);
}

__global__ __launch_bounds__(256) void gemm_o(
    const float* __restrict__ att,
    const float* __restrict__ Wo, const float* __restrict__ bo,
    float* __restrict__ out)
{
    gemm_body(att, Wo, bo, out, EE, RK, 1.f, blockIdx.y * 128, blockIdx.x * 128);
}

// ---------------------------------------------------------------------------
// Flash attention (unchanged from R5). One block = one (b, h, q-tile of 64).
// ---------------------------------------------------------------------------
__global__ __launch_bounds__(256) void flash_attn(const float* __restrict__ mask)
{
    __shared__ float Qs[64][33];
    __shared__ float Ks[64][33];
    __shared__ float Vs[64][32];
    __shared__ float Ps[64][65];

    const int b  = blockIdx.z;
    const int h  = blockIdx.y;
    const int qi = blockIdx.x;
    const int q0 = qi * 64;

    const int tid = threadIdx.x;
    const int row = tid >> 2;
    const int cg  = tid & 3;
    const int cbase = cg * 16;
    const int dvb   = cg * 8;

    for (int e = tid; e < 64 * 32; e += 256) {
        int r = e >> 5, d = e & 31;
        Qs[r][d] = g_q[((size_t)(b * SS + q0 + r)) * RK + h * DKQ + d];
    }

    float m_i = -INFINITY, l_i = 0.f;
    float o[8];
    #pragma unroll
    for (int j = 0; j < 8; j++) o[j] = 0.f;

    const int ntiles = qi + 1;  // causal
    for (int t = 0; t < ntiles; t++) {
        const int k0 = t * 64;
        __syncthreads();
        for (int e = tid; e < 64 * 32; e += 256) {
            int r = e >> 5, d = e & 31;
            size_t gi = ((size_t)(b * SS + k0 + r)) * RK + h * DKQ + d;
            Ks[r][d] = g_k[gi];
            Vs[r][d] = g_v[gi];
        }
        __syncthreads();

        float s[16];
        #pragma unroll
        for (int j = 0; j < 16; j++) s[j] = 0.f;
        #pragma unroll
        for (int d = 0; d < 32; d++) {
            float qd = Qs[row][d];
            #pragma unroll
            for (int j = 0; j < 16; j++)
                s[j] += qd * Ks[cbase + j][d];
        }

        const float* mrow = mask + ((size_t)b * SS + (q0 + row)) * SS + k0 + cbase;
        float tmax = -INFINITY;
        #pragma unroll
        for (int j = 0; j < 16; j++) {
            s[j] = fmaxf(s[j] + mrow[j], -3.402823466e38f);
            tmax = fmaxf(tmax, s[j]);
        }
        tmax = fmaxf(tmax, __shfl_xor_sync(0xffffffffu, tmax, 1));
        tmax = fmaxf(tmax, __shfl_xor_sync(0xffffffffu, tmax, 2));

        const float m_new = fmaxf(m_i, tmax);
        const float scale = __expf(m_i - m_new);

        float lsum = 0.f;
        #pragma unroll
        for (int j = 0; j < 16; j++) {
            float p = __expf(s[j] - m_new);
            Ps[row][cbase + j] = p;
            lsum += p;
        }
        lsum += __shfl_xor_sync(0xffffffffu, lsum, 1);
        lsum += __shfl_xor_sync(0xffffffffu, lsum, 2);

        l_i = l_i * scale + lsum;
        m_i = m_new;

        #pragma unroll
        for (int j = 0; j < 8; j++) o[j] *= scale;

        __syncwarp();
        for (int k = 0; k < 64; k++) {
            float p = Ps[row][k];
            #pragma unroll
            for (int j = 0; j < 8; j++)
                o[j] += p * Vs[k][dvb + j];
        }
        __syncwarp();
    }

    const float inv = 1.f / l_i;
    size_t ob = ((size_t)(b * SS + q0 + row)) * RK + h * DVV + dvb;
    #pragma unroll
    for (int j = 0; j < 8; j++)
        g_att[ob + j] = o[j] * inv;
}

// ---------------------------------------------------------------------------
extern "C" void kernel_launch(void* const* d_in, const int* in_sizes, int n_in,
                              void* d_out, int out_size)
{
    const float* hidden = (const float*)d_in[0];
    const float* mask   = (const float*)d_in[1];
    const float* Wq     = (const float*)d_in[2];
    const float* bq     = (const float*)d_in[3];
    const float* Wk     = (const float*)d_in[4];
    const float* bk     = (const float*)d_in[5];
    const float* Wv     = (const float*)d_in[6];
    const float* bv     = (const float*)d_in[7];
    const float* Wo     = (const float*)d_in[8];
    const float* bo     = (const float*)d_in[9];
    float* out = (float*)d_out;

    float* q = nullptr; float* k = nullptr; float* v = nullptr; float* att = nullptr;
    cudaGetSymbolAddress((void**)&q,   g_q);
    cudaGetSymbolAddress((void**)&k,   g_k);
    cudaGetSymbolAddress((void**)&v,   g_v);
    cudaGetSymbolAddress((void**)&att, g_att);

    const float scaling = 0.125f;  // 64^-0.5 (original head dim)

    // Fused projections: (4096 x 2048) @ (1024 x 2048)^T -> 3x (4096 x 1024)
    {
        dim3 grid(RK / 128, MM / 128, 3);
        gemm_qkv<<<grid, 256>>>(hidden, Wq, bq, Wk, bk, Wv, bv, q, k, v, scaling);
    }

    // Attention
    {
        dim3 grid(SS / 64, HH, BB);
        flash_attn<<<grid, 256>>>(mask);
    }

    // Output projection: (4096 x 1024) @ (2048 x 1024)^T -> (4096 x 2048)
    {
        dim3 grid(EE / 128, MM / 128);
        gemm_o<<<grid, 256>>>(att, Wo, bo, out);
    }
}

// round 8
// speedup vs baseline: 1.5453x; 1.0030x over previous
#include <cuda_runtime.h>
#include <math.h>
#include <stdint.h>

// Problem constants
#define BB   2
#define SS   2048
#define EE   2048
#define HH   32
#define DKQ  32
#define DVV  32
#define RK   1024
#define MM   (BB*SS)   // 4096

// Scratch (no cudaMalloc allowed)
__device__ float g_q[MM * RK];
__device__ float g_k[MM * RK];
__device__ float g_v[MM * RK];
__device__ float g_att[MM * RK];

// ---------------------------------------------------------------------------
// tf32 helpers
// ---------------------------------------------------------------------------
__device__ __forceinline__ uint32_t f2tf32(float x) {
    uint32_t r;
    asm("cvt.rna.tf32.f32 %0, %1;" : "=r"(r) : "f"(x));
    return r;
}

__device__ __forceinline__ void mma_tf32(float* c, const uint32_t* a, const uint32_t* b) {
    asm volatile(
        "mma.sync.aligned.m16n8k8.row.col.f32.tf32.tf32.f32 "
        "{%0,%1,%2,%3}, {%4,%5,%6,%7}, {%8,%9}, {%0,%1,%2,%3};"
        : "+f"(c[0]), "+f"(c[1]), "+f"(c[2]), "+f"(c[3])
        : "r"(a[0]), "r"(a[1]), "r"(a[2]), "r"(a[3]),
          "r"(b[0]), "r"(b[1]));
}

// ---------------------------------------------------------------------------
// tf32 tensor-core GEMM body:
//   C[m][n] = alpha * ( sum_k A[m][k]*W[n][k] + bias[n] )   (C = A @ W^T)
// Block tile 128x128, K-step 16. 256 threads = 8 warps in 2(M) x 4(N) grid,
// warp tile 64x32 = 4x4 grid of m16n8k8 MMAs.
// SMEM stride 20 floats: fragment loads hit all 32 banks (g*20+lq mod 32).
// Requires: Md % 128 == 0, Nd % 128 == 0, Kd % 16 == 0 (true for all calls).
// ---------------------------------------------------------------------------
__device__ __forceinline__ void gemm_body(
    const float* __restrict__ A, const float* __restrict__ W,
    const float* __restrict__ bias, float* __restrict__ C,
    int Nd, int Kd, float alpha, int bm, int bn)
{
    __shared__ uint32_t As[128][20];
    __shared__ uint32_t Bs[128][20];

    const int tid  = threadIdx.x;
    const int lane = tid & 31;
    const int warp = tid >> 5;
    const int g    = lane >> 2;      // 0..7
    const int lq   = lane & 3;       // 0..3
    const int wm   = (warp & 1) << 6;   // 0 or 64
    const int wn   = (warp >> 1) << 5;  // 0,32,64,96

    const int lrow = tid >> 2;          // 0..63
    const int lkg  = (tid & 3) << 2;    // 0,4,8,12

    const float* Ag0 = A + (size_t)(bm + lrow)      * Kd + lkg;
    const float* Ag1 = A + (size_t)(bm + lrow + 64) * Kd + lkg;
    const float* Wg0 = W + (size_t)(bn + lrow)      * Kd + lkg;
    const float* Wg1 = W + (size_t)(bn + lrow + 64) * Kd + lkg;

    float acc[4][4][4];
    #pragma unroll
    for (int i = 0; i < 4; i++)
        #pragma unroll
        for (int j = 0; j < 4; j++)
            #pragma unroll
            for (int e = 0; e < 4; e++) acc[i][j][e] = 0.f;

    // Prefetch first K-slab into registers
    float4 fa0 = *(const float4*)Ag0;
    float4 fa1 = *(const float4*)Ag1;
    float4 fb0 = *(const float4*)Wg0;
    float4 fb1 = *(const float4*)Wg1;

    for (int k0 = 0; k0 < Kd; k0 += 16) {
        // reg -> smem (convert to tf32 once per element here)
        As[lrow][lkg + 0] = f2tf32(fa0.x); As[lrow][lkg + 1] = f2tf32(fa0.y);
        As[lrow][lkg + 2] = f2tf32(fa0.z); As[lrow][lkg + 3] = f2tf32(fa0.w);
        As[lrow + 64][lkg + 0] = f2tf32(fa1.x); As[lrow + 64][lkg + 1] = f2tf32(fa1.y);
        As[lrow + 64][lkg + 2] = f2tf32(fa1.z); As[lrow + 64][lkg + 3] = f2tf32(fa1.w);
        Bs[lrow][lkg + 0] = f2tf32(fb0.x); Bs[lrow][lkg + 1] = f2tf32(fb0.y);
        Bs[lrow][lkg + 2] = f2tf32(fb0.z); Bs[lrow][lkg + 3] = f2tf32(fb0.w);
        Bs[lrow + 64][lkg + 0] = f2tf32(fb1.x); Bs[lrow + 64][lkg + 1] = f2tf32(fb1.y);
        Bs[lrow + 64][lkg + 2] = f2tf32(fb1.z); Bs[lrow + 64][lkg + 3] = f2tf32(fb1.w);
        __syncthreads();

        // prefetch next slab while MMAs run
        if (k0 + 16 < Kd) {
            Ag0 += 16; Ag1 += 16; Wg0 += 16; Wg1 += 16;
            fa0 = *(const float4*)Ag0;
            fa1 = *(const float4*)Ag1;
            fb0 = *(const float4*)Wg0;
            fb1 = *(const float4*)Wg1;
        }

        #pragma unroll
        for (int ks = 0; ks < 16; ks += 8) {
            uint32_t af[4][4], bf[4][2];
            #pragma unroll
            for (int i = 0; i < 4; i++) {
                const int r = wm + i * 16 + g;
                af[i][0] = As[r][ks + lq];
                af[i][1] = As[r + 8][ks + lq];
                af[i][2] = As[r][ks + lq + 4];
                af[i][3] = As[r + 8][ks + lq + 4];
            }
            #pragma unroll
            for (int j = 0; j < 4; j++) {
                const int n = wn + j * 8 + g;
                bf[j][0] = Bs[n][ks + lq];
                bf[j][1] = Bs[n][ks + lq + 4];
            }
            #pragma unroll
            for (int i = 0; i < 4; i++)
                #pragma unroll
                for (int j = 0; j < 4; j++)
                    mma_tf32(acc[i][j], af[i], bf[j]);
        }
        __syncthreads();
    }

    // Epilogue: C fragment layout m16n8: (g, 2*lq), (g, 2*lq+1), (g+8, ...)
    #pragma unroll
    for (int i = 0; i < 4; i++) {
        const int row = bm + wm + i * 16 + g;
        #pragma unroll
        for (int j = 0; j < 4; j++) {
            const int col = bn + wn + j * 8 + (lq << 1);
            const float b0 = bias[col], b1 = bias[col + 1];
            float* c0 = C + (size_t)row * Nd + col;
            float* c1 = C + (size_t)(row + 8) * Nd + col;
            c0[0] = alpha * (acc[i][j][0] + b0);
            c0[1] = alpha * (acc[i][j][1] + b1);
            c1[0] = alpha * (acc[i][j][2] + b0);
            c1[1] = alpha * (acc[i][j][3] + b1);
        }
    }
}

// Fused q/k/v projection: blockIdx.z selects the weight/bias/output triple.
__global__ __launch_bounds__(256) void gemm_qkv(
    const float* __restrict__ hidden,
    const float* __restrict__ Wq, const float* __restrict__ bq,
    const float* __restrict__ Wk, const float* __restrict__ bk,
    const float* __restrict__ Wv, const float* __restrict__ bv,
    float* __restrict__ q, float* __restrict__ k, float* __restrict__ v,
    float scaling)
{
    const float* W; const float* bias; float* C; float alpha;
    if (blockIdx.z == 0)      { W = Wq; bias = bq; C = q; alpha = scaling; }
    else if (blockIdx.z == 1) { W = Wk; bias = bk; C = k; alpha = 1.f; }
    else                      { W = Wv; bias = bv; C = v; alpha = 1.f; }
    gemm_body(hidden, W, bias, C, RK, EE, alpha, blockIdx.y * 128, blockIdx.x * 128);
}

__global__ __launch_bounds__(256) void gemm_o(
    const float* __restrict__ att,
    const float* __restrict__ Wo, const float* __restrict__ bo,
    float* __restrict__ out)
{
    gemm_body(att, Wo, bo, out, EE, RK, 1.f, blockIdx.y * 128, blockIdx.x * 128);
}

// ---------------------------------------------------------------------------
// Flash attention (unchanged from R5). One block = one (b, h, q-tile of 64).
// ---------------------------------------------------------------------------
__global__ __launch_bounds__(256) void flash_attn(const float* __restrict__ mask)
{
    __shared__ float Qs[64][33];
    __shared__ float Ks[64][33];
    __shared__ float Vs[64][32];
    __shared__ float Ps[64][65];

    const int b  = blockIdx.z;
    const int h  = blockIdx.y;
    const int qi = blockIdx.x;
    const int q0 = qi * 64;

    const int tid = threadIdx.x;
    const int row = tid >> 2;
    const int cg  = tid & 3;
    const int cbase = cg * 16;
    const int dvb   = cg * 8;

    for (int e = tid; e < 64 * 32; e += 256) {
        int r = e >> 5, d = e & 31;
        Qs[r][d] = g_q[((size_t)(b * SS + q0 + r)) * RK + h * DKQ + d];
    }

    float m_i = -INFINITY, l_i = 0.f;
    float o[8];
    #pragma unroll
    for (int j = 0; j < 8; j++) o[j] = 0.f;

    const int ntiles = qi + 1;  // causal
    for (int t = 0; t < ntiles; t++) {
        const int k0 = t * 64;
        __syncthreads();
        for (int e = tid; e < 64 * 32; e += 256) {
            int r = e >> 5, d = e & 31;
            size_t gi = ((size_t)(b * SS + k0 + r)) * RK + h * DKQ + d;
            Ks[r][d] = g_k[gi];
            Vs[r][d] = g_v[gi];
        }
        __syncthreads();

        float s[16];
        #pragma unroll
        for (int j = 0; j < 16; j++) s[j] = 0.f;
        #pragma unroll
        for (int d = 0; d < 32; d++) {
            float qd = Qs[row][d];
            #pragma unroll
            for (int j = 0; j < 16; j++)
                s[j] += qd * Ks[cbase + j][d];
        }

        const float* mrow = mask + ((size_t)b * SS + (q0 + row)) * SS + k0 + cbase;
        float tmax = -INFINITY;
        #pragma unroll
        for (int j = 0; j < 16; j++) {
            s[j] = fmaxf(s[j] + mrow[j], -3.402823466e38f);
            tmax = fmaxf(tmax, s[j]);
        }
        tmax = fmaxf(tmax, __shfl_xor_sync(0xffffffffu, tmax, 1));
        tmax = fmaxf(tmax, __shfl_xor_sync(0xffffffffu, tmax, 2));

        const float m_new = fmaxf(m_i, tmax);
        const float scale = __expf(m_i - m_new);

        float lsum = 0.f;
        #pragma unroll
        for (int j = 0; j < 16; j++) {
            float p = __expf(s[j] - m_new);
            Ps[row][cbase + j] = p;
            lsum += p;
        }
        lsum += __shfl_xor_sync(0xffffffffu, lsum, 1);
        lsum += __shfl_xor_sync(0xffffffffu, lsum, 2);

        l_i = l_i * scale + lsum;
        m_i = m_new;

        #pragma unroll
        for (int j = 0; j < 8; j++) o[j] *= scale;

        __syncwarp();
        for (int k = 0; k < 64; k++) {
            float p = Ps[row][k];
            #pragma unroll
            for (int j = 0; j < 8; j++)
                o[j] += p * Vs[k][dvb + j];
        }
        __syncwarp();
    }

    const float inv = 1.f / l_i;
    size_t ob = ((size_t)(b * SS + q0 + row)) * RK + h * DVV + dvb;
    #pragma unroll
    for (int j = 0; j < 8; j++)
        g_att[ob + j] = o[j] * inv;
}

// ---------------------------------------------------------------------------
extern "C" void kernel_launch(void* const* d_in, const int* in_sizes, int n_in,
                              void* d_out, int out_size)
{
    const float* hidden = (const float*)d_in[0];
    const float* mask   = (const float*)d_in[1];
    const float* Wq     = (const float*)d_in[2];
    const float* bq     = (const float*)d_in[3];
    const float* Wk     = (const float*)d_in[4];
    const float* bk     = (const float*)d_in[5];
    const float* Wv     = (const float*)d_in[6];
    const float* bv     = (const float*)d_in[7];
    const float* Wo     = (const float*)d_in[8];
    const float* bo     = (const float*)d_in[9];
    float* out = (float*)d_out;

    float* q = nullptr; float* k = nullptr; float* v = nullptr; float* att = nullptr;
    cudaGetSymbolAddress((void**)&q,   g_q);
    cudaGetSymbolAddress((void**)&k,   g_k);
    cudaGetSymbolAddress((void**)&v,   g_v);
    cudaGetSymbolAddress((void**)&att, g_att);

    const float scaling = 0.125f;  // 64^-0.5 (original head dim)

    // Fused projections: (4096 x 2048) @ (1024 x 2048)^T -> 3x (4096 x 1024)
    {
        dim3 grid(RK / 128, MM / 128, 3);
        gemm_qkv<<<grid, 256>>>(hidden, Wq, bq, Wk, bk, Wv, bv, q, k, v, scaling);
    }

    // Attention
    {
        dim3 grid(SS / 64, HH, BB);
        flash_attn<<<grid, 256>>>(mask);
    }

    // Output projection: (4096 x 1024) @ (2048 x 1024)^T -> (4096 x 2048)
    {
        dim3 grid(EE / 128, MM / 128);
        gemm_o<<<grid, 256>>>(att, Wo, bo, out);
    }
}

// round 9
// speedup vs baseline: 1.5508x; 1.0035x over previous
#include <cuda_runtime.h>
#include <math.h>
#include <stdint.h>

// Problem constants
#define BB   2
#define SS   2048
#define EE   2048
#define HH   32
#define DKQ  32
#define DVV  32
#define RK   1024
#define MM   (BB*SS)   // 4096

// Scratch (no cudaMalloc allowed)
__device__ float g_q[MM * RK];
__device__ float g_k[MM * RK];
__device__ float g_v[MM * RK];
__device__ float g_att[MM * RK];

// ---------------------------------------------------------------------------
// tf32 helpers
// ---------------------------------------------------------------------------
__device__ __forceinline__ uint32_t f2tf32(float x) {
    uint32_t r;
    asm("cvt.rna.tf32.f32 %0, %1;" : "=r"(r) : "f"(x));
    return r;
}

__device__ __forceinline__ void mma_tf32(float* c, const uint32_t* a, const uint32_t* b) {
    asm volatile(
        "mma.sync.aligned.m16n8k8.row.col.f32.tf32.tf32.f32 "
        "{%0,%1,%2,%3}, {%4,%5,%6,%7}, {%8,%9}, {%0,%1,%2,%3};"
        : "+f"(c[0]), "+f"(c[1]), "+f"(c[2]), "+f"(c[3])
        : "r"(a[0]), "r"(a[1]), "r"(a[2]), "r"(a[3]),
          "r"(b[0]), "r"(b[1]));
}

// ---------------------------------------------------------------------------
// tf32 tensor-core GEMM body:
//   C[m][n] = alpha * ( sum_k A[m][k]*W[n][k] + bias[n] )   (C = A @ W^T)
// Block tile 128x128, K-step 16. 256 threads = 8 warps in 2(M) x 4(N) grid,
// warp tile 64x32 = 4x4 grid of m16n8k8 MMAs.
// SMEM stride 20 floats: fragment loads hit all 32 banks (g*20+lq mod 32).
// Requires: Md % 128 == 0, Nd % 128 == 0, Kd % 16 == 0 (true for all calls).
// ---------------------------------------------------------------------------
__device__ __forceinline__ void gemm_body(
    const float* __restrict__ A, const float* __restrict__ W,
    const float* __restrict__ bias, float* __restrict__ C,
    int Nd, int Kd, float alpha, int bm, int bn)
{
    __shared__ uint32_t As[128][20];
    __shared__ uint32_t Bs[128][20];

    const int tid  = threadIdx.x;
    const int lane = tid & 31;
    const int warp = tid >> 5;
    const int g    = lane >> 2;      // 0..7
    const int lq   = lane & 3;       // 0..3
    const int wm   = (warp & 1) << 6;   // 0 or 64
    const int wn   = (warp >> 1) << 5;  // 0,32,64,96

    const int lrow = tid >> 2;          // 0..63
    const int lkg  = (tid & 3) << 2;    // 0,4,8,12

    const float* Ag0 = A + (size_t)(bm + lrow)      * Kd + lkg;
    const float* Ag1 = A + (size_t)(bm + lrow + 64) * Kd + lkg;
    const float* Wg0 = W + (size_t)(bn + lrow)      * Kd + lkg;
    const float* Wg1 = W + (size_t)(bn + lrow + 64) * Kd + lkg;

    float acc[4][4][4];
    #pragma unroll
    for (int i = 0; i < 4; i++)
        #pragma unroll
        for (int j = 0; j < 4; j++)
            #pragma unroll
            for (int e = 0; e < 4; e++) acc[i][j][e] = 0.f;

    // Prefetch first K-slab into registers
    float4 fa0 = *(const float4*)Ag0;
    float4 fa1 = *(const float4*)Ag1;
    float4 fb0 = *(const float4*)Wg0;
    float4 fb1 = *(const float4*)Wg1;

    for (int k0 = 0; k0 < Kd; k0 += 16) {
        // reg -> smem (convert to tf32 once per element here)
        As[lrow][lkg + 0] = f2tf32(fa0.x); As[lrow][lkg + 1] = f2tf32(fa0.y);
        As[lrow][lkg + 2] = f2tf32(fa0.z); As[lrow][lkg + 3] = f2tf32(fa0.w);
        As[lrow + 64][lkg + 0] = f2tf32(fa1.x); As[lrow + 64][lkg + 1] = f2tf32(fa1.y);
        As[lrow + 64][lkg + 2] = f2tf32(fa1.z); As[lrow + 64][lkg + 3] = f2tf32(fa1.w);
        Bs[lrow][lkg + 0] = f2tf32(fb0.x); Bs[lrow][lkg + 1] = f2tf32(fb0.y);
        Bs[lrow][lkg + 2] = f2tf32(fb0.z); Bs[lrow][lkg + 3] = f2tf32(fb0.w);
        Bs[lrow + 64][lkg + 0] = f2tf32(fb1.x); Bs[lrow + 64][lkg + 1] = f2tf32(fb1.y);
        Bs[lrow + 64][lkg + 2] = f2tf32(fb1.z); Bs[lrow + 64][lkg + 3] = f2tf32(fb1.w);
        __syncthreads();

        // prefetch next slab while MMAs run
        if (k0 + 16 < Kd) {
            Ag0 += 16; Ag1 += 16; Wg0 += 16; Wg1 += 16;
            fa0 = *(const float4*)Ag0;
            fa1 = *(const float4*)Ag1;
            fb0 = *(const float4*)Wg0;
            fb1 = *(const float4*)Wg1;
        }

        #pragma unroll
        for (int ks = 0; ks < 16; ks += 8) {
            uint32_t af[4][4], bf[4][2];
            #pragma unroll
            for (int i = 0; i < 4; i++) {
                const int r = wm + i * 16 + g;
                af[i][0] = As[r][ks + lq];
                af[i][1] = As[r + 8][ks + lq];
                af[i][2] = As[r][ks + lq + 4];
                af[i][3] = As[r + 8][ks + lq + 4];
            }
            #pragma unroll
            for (int j = 0; j < 4; j++) {
                const int n = wn + j * 8 + g;
                bf[j][0] = Bs[n][ks + lq];
                bf[j][1] = Bs[n][ks + lq + 4];
            }
            #pragma unroll
            for (int i = 0; i < 4; i++)
                #pragma unroll
                for (int j = 0; j < 4; j++)
                    mma_tf32(acc[i][j], af[i], bf[j]);
        }
        __syncthreads();
    }

    // Epilogue: C fragment layout m16n8: (g, 2*lq), (g, 2*lq+1), (g+8, ...)
    #pragma unroll
    for (int i = 0; i < 4; i++) {
        const int row = bm + wm + i * 16 + g;
        #pragma unroll
        for (int j = 0; j < 4; j++) {
            const int col = bn + wn + j * 8 + (lq << 1);
            const float b0 = bias[col], b1 = bias[col + 1];
            float* c0 = C + (size_t)row * Nd + col;
            float* c1 = C + (size_t)(row + 8) * Nd + col;
            c0[0] = alpha * (acc[i][j][0] + b0);
            c0[1] = alpha * (acc[i][j][1] + b1);
            c1[0] = alpha * (acc[i][j][2] + b0);
            c1[1] = alpha * (acc[i][j][3] + b1);
        }
    }
}

// Fused q/k/v projection: blockIdx.z selects the weight/bias/output triple.
__global__ __launch_bounds__(256) void gemm_qkv(
    const float* __restrict__ hidden,
    const float* __restrict__ Wq, const float* __restrict__ bq,
    const float* __restrict__ Wk, const float* __restrict__ bk,
    const float* __restrict__ Wv, const float* __restrict__ bv,
    float* __restrict__ q, float* __restrict__ k, float* __restrict__ v,
    float scaling)
{
    const float* W; const float* bias; float* C; float alpha;
    if (blockIdx.z == 0)      { W = Wq; bias = bq; C = q; alpha = scaling; }
    else if (blockIdx.z == 1) { W = Wk; bias = bk; C = k; alpha = 1.f; }
    else                      { W = Wv; bias = bv; C = v; alpha = 1.f; }
    gemm_body(hidden, W, bias, C, RK, EE, alpha, blockIdx.y * 128, blockIdx.x * 128);
}

__global__ __launch_bounds__(256) void gemm_o(
    const float* __restrict__ att,
    const float* __restrict__ Wo, const float* __restrict__ bo,
    float* __restrict__ out)
{
    gemm_body(att, Wo, bo, out, EE, RK, 1.f, blockIdx.y * 128, blockIdx.x * 128);
}

// ---------------------------------------------------------------------------
// Flash attention (unchanged from R5). One block = one (b, h, q-tile of 64).
// ---------------------------------------------------------------------------
__global__ __launch_bounds__(256) void flash_attn(const float* __restrict__ mask)
{
    __shared__ float Qs[64][33];
    __shared__ float Ks[64][33];
    __shared__ float Vs[64][32];
    __shared__ float Ps[64][65];

    const int b  = blockIdx.z;
    const int h  = blockIdx.y;
    const int qi = blockIdx.x;
    const int q0 = qi * 64;

    const int tid = threadIdx.x;
    const int row = tid >> 2;
    const int cg  = tid & 3;
    const int cbase = cg * 16;
    const int dvb   = cg * 8;

    for (int e = tid; e < 64 * 32; e += 256) {
        int r = e >> 5, d = e & 31;
        Qs[r][d] = g_q[((size_t)(b * SS + q0 + r)) * RK + h * DKQ + d];
    }

    float m_i = -INFINITY, l_i = 0.f;
    float o[8];
    #pragma unroll
    for (int j = 0; j < 8; j++) o[j] = 0.f;

    const int ntiles = qi + 1;  // causal
    for (int t = 0; t < ntiles; t++) {
        const int k0 = t * 64;
        __syncthreads();
        for (int e = tid; e < 64 * 32; e += 256) {
            int r = e >> 5, d = e & 31;
            size_t gi = ((size_t)(b * SS + k0 + r)) * RK + h * DKQ + d;
            Ks[r][d] = g_k[gi];
            Vs[r][d] = g_v[gi];
        }
        __syncthreads();

        float s[16];
        #pragma unroll
        for (int j = 0; j < 16; j++) s[j] = 0.f;
        #pragma unroll
        for (int d = 0; d < 32; d++) {
            float qd = Qs[row][d];
            #pragma unroll
            for (int j = 0; j < 16; j++)
                s[j] += qd * Ks[cbase + j][d];
        }

        const float* mrow = mask + ((size_t)b * SS + (q0 + row)) * SS + k0 + cbase;
        float tmax = -INFINITY;
        #pragma unroll
        for (int j = 0; j < 16; j++) {
            s[j] = fmaxf(s[j] + mrow[j], -3.402823466e38f);
            tmax = fmaxf(tmax, s[j]);
        }
        tmax = fmaxf(tmax, __shfl_xor_sync(0xffffffffu, tmax, 1));
        tmax = fmaxf(tmax, __shfl_xor_sync(0xffffffffu, tmax, 2));

        const float m_new = fmaxf(m_i, tmax);
        const float scale = __expf(m_i - m_new);

        float lsum = 0.f;
        #pragma unroll
        for (int j = 0; j < 16; j++) {
            float p = __expf(s[j] - m_new);
            Ps[row][cbase + j] = p;
            lsum += p;
        }
        lsum += __shfl_xor_sync(0xffffffffu, lsum, 1);
        lsum += __shfl_xor_sync(0xffffffffu, lsum, 2);

        l_i = l_i * scale + lsum;
        m_i = m_new;

        #pragma unroll
        for (int j = 0; j < 8; j++) o[j] *= scale;

        __syncwarp();
        for (int k = 0; k < 64; k++) {
            float p = Ps[row][k];
            #pragma unroll
            for (int j = 0; j < 8; j++)
                o[j] += p * Vs[k][dvb + j];
        }
        __syncwarp();
    }

    const float inv = 1.f / l_i;
    size_t ob = ((size_t)(b * SS + q0 + row)) * RK + h * DVV + dvb;
    #pragma unroll
    for (int j = 0; j < 8; j++)
        g_att[ob + j] = o[j] * inv;
}

// ---------------------------------------------------------------------------
extern "C" void kernel_launch(void* const* d_in, const int* in_sizes, int n_in,
                              void* d_out, int out_size)
{
    const float* hidden = (const float*)d_in[0];
    const float* mask   = (const float*)d_in[1];
    const float* Wq     = (const float*)d_in[2];
    const float* bq     = (const float*)d_in[3];
    const float* Wk     = (const float*)d_in[4];
    const float* bk     = (const float*)d_in[5];
    const float* Wv     = (const float*)d_in[6];
    const float* bv     = (const float*)d_in[7];
    const float* Wo     = (const float*)d_in[8];
    const float* bo     = (const float*)d_in[9];
    float* out = (float*)d_out;

    float* q = nullptr; float* k = nullptr; float* v = nullptr; float* att = nullptr;
    cudaGetSymbolAddress((void**)&q,   g_q);
    cudaGetSymbolAddress((void**)&k,   g_k);
    cudaGetSymbolAddress((void**)&v,   g_v);
    cudaGetSymbolAddress((void**)&att, g_att);

    const float scaling = 0.125f;  // 64^-0.5 (original head dim)

    // Fused projections: (4096 x 2048) @ (1024 x 2048)^T -> 3x (4096 x 1024)
    {
        dim3 grid(RK / 128, MM / 128, 3);
        gemm_qkv<<<grid, 256>>>(hidden, Wq, bq, Wk, bk, Wv, bv, q, k, v, scaling);
    }

    // Attention
    {
        dim3 grid(SS / 64, HH, BB);
        flash_attn<<<grid, 256>>>(mask);
    }

    // Output projection: (4096 x 1024) @ (2048 x 1024)^T -> (4096 x 2048)
    {
        dim3 grid(EE / 128, MM / 128);
        gemm_o<<<grid, 256>>>(att, Wo, bo, out);
    }
}